// round 3
// baseline (speedup 1.0000x reference)
#include <cuda_runtime.h>
#include <cuda_bf16.h>
#include <cstdint>

// Problem constants (fixed by the reference)
#define NS 100000
#define NP 20000
#define NE 500000
#define FH 128

// ---------------- device scratch (static allocation only) ----------------
__device__ float g_xplay[NP * FH];
__device__ float g_aggP [NP * FH];
__device__ float g_aggS [NS * FH];
__device__ float g_p1   [NP * FH];
__device__ float g_s1   [NS * FH];

__device__ int g_cntP[NP], g_curP[NP];
__device__ int g_cntS[NS], g_curS[NS];
__device__ int g_rpP[NP + 1];
__device__ int g_rpS[NS + 1];
__device__ int g_csrP[NE];   // song ids grouped by playlist
__device__ int g_csrS[NE];   // playlist ids grouped by song

// ---------------- CSR build ----------------
__global__ void zero_misc_kernel() {
    int i = blockIdx.x * blockDim.x + threadIdx.x;
    if (i < NS) { g_cntS[i] = 0; g_curS[i] = 0; }
    if (i < NP) { g_cntP[i] = 0; g_curP[i] = 0; }
}

__global__ void hist_kernel(const int* __restrict__ es, const int* __restrict__ ep) {
    int i = blockIdx.x * blockDim.x + threadIdx.x;
    if (i < NE) {
        atomicAdd(&g_cntS[es[i]], 1);
        atomicAdd(&g_cntP[ep[i]], 1);
    }
}

// single-block exclusive scan: cnt[0..n) -> rowptr[0..n]
__global__ void scan_kernel(const int* __restrict__ cnt, int* __restrict__ rowptr, int n) {
    __shared__ int ssums[1024];
    int tid = threadIdx.x;
    int per = (n + 1023) / 1024;
    int start = tid * per;
    int end = start + per; if (end > n) end = n;
    int local = 0;
    for (int i = start; i < end; ++i) local += cnt[i];
    ssums[tid] = local;
    __syncthreads();
    for (int off = 1; off < 1024; off <<= 1) {
        int add = (tid >= off) ? ssums[tid - off] : 0;
        __syncthreads();
        ssums[tid] += add;
        __syncthreads();
    }
    int run = (tid > 0) ? ssums[tid - 1] : 0;   // exclusive prefix of this chunk
    for (int i = start; i < end; ++i) { rowptr[i] = run; run += cnt[i]; }
    if (tid == 1023) rowptr[n] = ssums[1023];
}

__global__ void fill_kernel(const int* __restrict__ es, const int* __restrict__ ep) {
    int i = blockIdx.x * blockDim.x + threadIdx.x;
    if (i < NE) {
        int s = es[i], p = ep[i];
        int posP = atomicAdd(&g_curP[p], 1);
        g_csrP[g_rpP[p] + posP] = s;
        int posS = atomicAdd(&g_curS[s], 1);
        g_csrS[g_rpS[s] + posS] = p;
    }
}

// x_play = playlist_embed[playlist_node_id]
__global__ void gather_xplay_kernel(const float* __restrict__ pemb, const int* __restrict__ pid) {
    int i = blockIdx.x * blockDim.x + threadIdx.x;   // NP * 32 threads, float4 each
    if (i < NP * 32) {
        int row = i >> 5;
        int q = i & 31;
        int src = pid[row];
        float4 v = *(const float4*)(pemb + (size_t)src * FH + q * 4);
        *(float4*)(g_xplay + (size_t)row * FH + q * 4) = v;
    }
}

// ---------------- mean aggregation (warp per destination row) ----------------
__global__ void agg_mean_kernel(const float* __restrict__ src,
                                const int* __restrict__ rowptr,
                                const int* __restrict__ cols,
                                float* __restrict__ out, int nrows) {
    int warp = (blockIdx.x * blockDim.x + threadIdx.x) >> 5;
    int lane = threadIdx.x & 31;
    if (warp >= nrows) return;
    int beg = rowptr[warp], end = rowptr[warp + 1];
    float4 acc = make_float4(0.f, 0.f, 0.f, 0.f);
    int e = beg;
    for (; e + 1 < end; e += 2) {
        int c0 = cols[e], c1 = cols[e + 1];
        float4 v0 = *(const float4*)(src + (size_t)c0 * FH + lane * 4);
        float4 v1 = *(const float4*)(src + (size_t)c1 * FH + lane * 4);
        acc.x += v0.x + v1.x; acc.y += v0.y + v1.y;
        acc.z += v0.z + v1.z; acc.w += v0.w + v1.w;
    }
    if (e < end) {
        int c0 = cols[e];
        float4 v0 = *(const float4*)(src + (size_t)c0 * FH + lane * 4);
        acc.x += v0.x; acc.y += v0.y; acc.z += v0.z; acc.w += v0.w;
    }
    int d = end - beg;
    float inv = 1.f / (float)(d > 0 ? d : 1);
    acc.x *= inv; acc.y *= inv; acc.z *= inv; acc.w *= inv;
    *(float4*)(out + (size_t)warp * FH + lane * 4) = acc;
}

// ---------------- 3xTF32 GEMM: out[M,128] = A0@W0 + A1@W1 + b (opt relu) ----------------
__device__ __forceinline__ void split_tf32(float f, unsigned& hi, unsigned& lo) {
    unsigned h;
    asm("cvt.rna.tf32.f32 %0, %1;" : "=r"(h) : "f"(f));
    float l = f - __uint_as_float(h);
    unsigned lw;
    asm("cvt.rna.tf32.f32 %0, %1;" : "=r"(lw) : "f"(l));
    hi = h; lo = lw;
}

#define MMA_TF32(acc, a, b0, b1)                                                   \
    asm volatile("mma.sync.aligned.m16n8k8.row.col.f32.tf32.tf32.f32 "             \
                 "{%0,%1,%2,%3},{%4,%5,%6,%7},{%8,%9},{%0,%1,%2,%3};"              \
                 : "+f"(acc[0]), "+f"(acc[1]), "+f"(acc[2]), "+f"(acc[3])          \
                 : "r"(a[0]), "r"(a[1]), "r"(a[2]), "r"(a[3]), "r"(b0), "r"(b1))

#define AS_LD 44   // padded stride for A smem (conflict-free fragment loads)
#define BS_LD 136  // padded stride for B smem

__global__ __launch_bounds__(256)
void gemm_dual_kernel(const float* __restrict__ A0, const float* __restrict__ A1,
                      const float* __restrict__ W0, const float* __restrict__ W1,
                      const float* __restrict__ bias,
                      float* __restrict__ out, int M, int do_relu) {
    __shared__ float As[128 * AS_LD];
    __shared__ float Bs[32 * BS_LD];
    __shared__ float bias_s[128];

    int tid = threadIdx.x;
    int lane = tid & 31;
    int wid = tid >> 5;
    int warp_m = wid & 3;    // 4 warps along M (32 rows each)
    int warp_n = wid >> 2;   // 2 warps along N (64 cols each)
    int g = lane >> 2;       // groupID
    int r = lane & 3;        // thread in group
    int blockRow = blockIdx.x * 128;

    if (tid < 128) bias_s[tid] = bias[tid];

    float acc[2][8][4];
#pragma unroll
    for (int mt = 0; mt < 2; ++mt)
#pragma unroll
        for (int nt = 0; nt < 8; ++nt)
#pragma unroll
            for (int j = 0; j < 4; ++j) acc[mt][nt][j] = 0.f;

#pragma unroll
    for (int seg = 0; seg < 2; ++seg) {
        const float* Aseg = seg ? A1 : A0;
        const float* Wseg = seg ? W1 : W0;
#pragma unroll
        for (int kc = 0; kc < 4; ++kc) {
            __syncthreads();
            // load A tile [128 rows x 32 k] (fp32)
#pragma unroll
            for (int rr = 0; rr < 4; ++rr) {
                int idx = rr * 256 + tid;      // 0..1023 float4 slots
                int m = idx >> 3;
                int kq = idx & 7;
                int grow = blockRow + m;
                float4 v = make_float4(0.f, 0.f, 0.f, 0.f);
                if (grow < M)
                    v = *(const float4*)(Aseg + (size_t)grow * 128 + kc * 32 + kq * 4);
                *(float4*)(&As[m * AS_LD + kq * 4]) = v;
            }
            // load W tile [32 k x 128 n]
#pragma unroll
            for (int rr = 0; rr < 4; ++rr) {
                int idx = rr * 256 + tid;
                int kr = idx >> 5;
                int nq = idx & 31;
                float4 v = *(const float4*)(Wseg + (size_t)(kc * 32 + kr) * 128 + nq * 4);
                *(float4*)(&Bs[kr * BS_LD + nq * 4]) = v;
            }
            __syncthreads();

#pragma unroll
            for (int k8 = 0; k8 < 4; ++k8) {
                int k0 = k8 * 8;
                unsigned ahi[2][4], alo[2][4];
#pragma unroll
                for (int mt = 0; mt < 2; ++mt) {
                    int mb = warp_m * 32 + mt * 16;
                    float f0 = As[(mb + g) * AS_LD + k0 + r];
                    float f1 = As[(mb + g + 8) * AS_LD + k0 + r];
                    float f2 = As[(mb + g) * AS_LD + k0 + r + 4];
                    float f3 = As[(mb + g + 8) * AS_LD + k0 + r + 4];
                    split_tf32(f0, ahi[mt][0], alo[mt][0]);
                    split_tf32(f1, ahi[mt][1], alo[mt][1]);
                    split_tf32(f2, ahi[mt][2], alo[mt][2]);
                    split_tf32(f3, ahi[mt][3], alo[mt][3]);
                }
#pragma unroll
                for (int nt = 0; nt < 8; ++nt) {
                    int nb = warp_n * 64 + nt * 8;
                    float fb0 = Bs[(k0 + r) * BS_LD + nb + g];
                    float fb1 = Bs[(k0 + r + 4) * BS_LD + nb + g];
                    unsigned bh0, bl0, bh1, bl1;
                    split_tf32(fb0, bh0, bl0);
                    split_tf32(fb1, bh1, bl1);
#pragma unroll
                    for (int mt = 0; mt < 2; ++mt) {
                        MMA_TF32(acc[mt][nt], ahi[mt], bh0, bh1);   // hi*hi
                        MMA_TF32(acc[mt][nt], ahi[mt], bl0, bl1);   // hi*lo
                        MMA_TF32(acc[mt][nt], alo[mt], bh0, bh1);   // lo*hi
                    }
                }
            }
        }
    }

    // epilogue
#pragma unroll
    for (int mt = 0; mt < 2; ++mt) {
#pragma unroll
        for (int nt = 0; nt < 8; ++nt) {
            int col = warp_n * 64 + nt * 8 + r * 2;
            float bv0 = bias_s[col], bv1 = bias_s[col + 1];
            int row0 = blockRow + warp_m * 32 + mt * 16 + g;
            int row1 = row0 + 8;
            float v0 = acc[mt][nt][0] + bv0;
            float v1 = acc[mt][nt][1] + bv1;
            float v2 = acc[mt][nt][2] + bv0;
            float v3 = acc[mt][nt][3] + bv1;
            if (do_relu) {
                v0 = fmaxf(v0, 0.f); v1 = fmaxf(v1, 0.f);
                v2 = fmaxf(v2, 0.f); v3 = fmaxf(v3, 0.f);
            }
            if (row0 < M) *(float2*)(out + (size_t)row0 * 128 + col) = make_float2(v0, v1);
            if (row1 < M) *(float2*)(out + (size_t)row1 * 128 + col) = make_float2(v2, v3);
        }
    }
}

// ---------------- host launcher ----------------
static float* sym_f(const void* s) { void* p = nullptr; cudaGetSymbolAddress(&p, s); return (float*)p; }
static int*   sym_i(const void* s) { void* p = nullptr; cudaGetSymbolAddress(&p, s); return (int*)p; }

extern "C" void kernel_launch(void* const* d_in, const int* in_sizes, int n_in,
                              void* d_out, int out_size) {
    const float* song_x  = (const float*)d_in[0];
    const int*   pid     = (const int*)d_in[1];
    const int*   e_song  = (const int*)d_in[2];
    const int*   e_play  = (const int*)d_in[3];
    const float* pemb    = (const float*)d_in[4];
    const float* Wl1_sp  = (const float*)d_in[5];
    const float* Wr1_sp  = (const float*)d_in[6];
    const float* b1_sp   = (const float*)d_in[7];
    const float* Wl1_ps  = (const float*)d_in[8];
    const float* Wr1_ps  = (const float*)d_in[9];
    const float* b1_ps   = (const float*)d_in[10];
    const float* Wl2_sp  = (const float*)d_in[11];
    const float* Wr2_sp  = (const float*)d_in[12];
    const float* b2_sp   = (const float*)d_in[13];
    const float* Wl2_ps  = (const float*)d_in[14];
    const float* Wr2_ps  = (const float*)d_in[15];
    const float* b2_ps   = (const float*)d_in[16];

    float* out = (float*)d_out;
    float* out_s2 = out;                      // [NS,128] first
    float* out_p2 = out + (size_t)NS * FH;    // [NP,128] second

    float* xplay = sym_f(g_xplay);
    float* aggP  = sym_f(g_aggP);
    float* aggS  = sym_f(g_aggS);
    float* p1    = sym_f(g_p1);
    float* s1    = sym_f(g_s1);
    int*   cntP  = sym_i(g_cntP);
    int*   cntS  = sym_i(g_cntS);
    int*   rpP   = sym_i(g_rpP);
    int*   rpS   = sym_i(g_rpS);
    int*   csrP  = sym_i(g_csrP);
    int*   csrS  = sym_i(g_csrS);

    // ---- CSR build (shared by both layers) ----
    zero_misc_kernel<<<(NS + 255) / 256, 256>>>();
    hist_kernel<<<(NE + 255) / 256, 256>>>(e_song, e_play);
    scan_kernel<<<1, 1024>>>(cntP, rpP, NP);
    scan_kernel<<<1, 1024>>>(cntS, rpS, NS);
    fill_kernel<<<(NE + 255) / 256, 256>>>(e_song, e_play);
    gather_xplay_kernel<<<(NP * 32 + 255) / 256, 256>>>(pemb, pid);

    const int AGG_WPB = 8;  // warps per block
    // ---- conv1 ----
    agg_mean_kernel<<<(NP + AGG_WPB - 1) / AGG_WPB, AGG_WPB * 32>>>(song_x, rpP, csrP, aggP, NP);
    gemm_dual_kernel<<<(NP + 127) / 128, 256>>>(aggP, xplay, Wl1_sp, Wr1_sp, b1_sp, p1, NP, 1);
    agg_mean_kernel<<<(NS + AGG_WPB - 1) / AGG_WPB, AGG_WPB * 32>>>(xplay, rpS, csrS, aggS, NS);
    gemm_dual_kernel<<<(NS + 127) / 128, 256>>>(aggS, song_x, Wl1_ps, Wr1_ps, b1_ps, s1, NS, 1);

    // ---- conv2 ----
    agg_mean_kernel<<<(NP + AGG_WPB - 1) / AGG_WPB, AGG_WPB * 32>>>(s1, rpP, csrP, aggP, NP);
    gemm_dual_kernel<<<(NP + 127) / 128, 256>>>(aggP, p1, Wl2_sp, Wr2_sp, b2_sp, out_p2, NP, 0);
    agg_mean_kernel<<<(NS + AGG_WPB - 1) / AGG_WPB, AGG_WPB * 32>>>(p1, rpS, csrS, aggS, NS);
    gemm_dual_kernel<<<(NS + 127) / 128, 256>>>(aggS, s1, Wl2_ps, Wr2_ps, b2_ps, out_s2, NS, 0);

    (void)in_sizes; (void)n_in; (void)out_size;
}

// round 7
// speedup vs baseline: 1.1540x; 1.1540x over previous
#include <cuda_runtime.h>
#include <cuda_bf16.h>
#include <cstdint>

// Problem constants (fixed by the reference)
#define NS 100000
#define NP 20000
#define NE 500000
#define FH 128

// ---------------- device scratch (static allocation only) ----------------
__device__ float g_xplay[NP * FH];
__device__ float g_aggP [NP * FH];
__device__ float g_aggS [NS * FH];
__device__ float g_p1   [NP * FH];
__device__ float g_s1   [NS * FH];

__device__ int g_cntP[NP], g_curP[NP];
__device__ int g_cntS[NS], g_curS[NS];
__device__ int g_rpP[NP + 1];
__device__ int g_rpS[NS + 1];
__device__ int g_csrP[NE];   // song ids grouped by playlist
__device__ int g_csrS[NE];   // playlist ids grouped by song
__device__ int g_part[256];  // block partial sums for multi-block scan

// ---------------- CSR build ----------------
__global__ void zero_misc_kernel() {
    int i = blockIdx.x * blockDim.x + threadIdx.x;
    if (i < NS) { g_cntS[i] = 0; g_curS[i] = 0; }
    if (i < NP) { g_cntP[i] = 0; g_curP[i] = 0; }
}

__global__ void hist_kernel(const int* __restrict__ es, const int* __restrict__ ep) {
    int i = blockIdx.x * blockDim.x + threadIdx.x;
    if (i < NE) {
        atomicAdd(&g_cntS[es[i]], 1);
        atomicAdd(&g_cntP[ep[i]], 1);
    }
}

// ---- multi-block exclusive scan: cnt[0..n) -> rowptr[0..n] ----
// pass 1: block-local exclusive scan over 512-elem chunks; block total -> g_part
__global__ void scan1_kernel(const int* __restrict__ cnt, int* __restrict__ rowptr, int n) {
    __shared__ int s[512];
    int tid = threadIdx.x;
    int i = blockIdx.x * 512 + tid;
    int v = (i < n) ? cnt[i] : 0;
    s[tid] = v;
    __syncthreads();
#pragma unroll
    for (int off = 1; off < 512; off <<= 1) {
        int a = (tid >= off) ? s[tid - off] : 0;
        __syncthreads();
        s[tid] += a;
        __syncthreads();
    }
    if (i < n) rowptr[i] = s[tid] - v;       // exclusive within block
    if (tid == 511) g_part[blockIdx.x] = s[511];
}

// pass 2: single small block scans the (<=256) block totals (inclusive)
__global__ void scan2_kernel(int nb) {
    __shared__ int s[256];
    int tid = threadIdx.x;
    s[tid] = (tid < nb) ? g_part[tid] : 0;
    __syncthreads();
#pragma unroll
    for (int off = 1; off < 256; off <<= 1) {
        int a = (tid >= off) ? s[tid - off] : 0;
        __syncthreads();
        s[tid] += a;
        __syncthreads();
    }
    if (tid < nb) g_part[tid] = s[tid];
}

// pass 3: add block offsets; write rowptr[n]
__global__ void scan3_kernel(int* __restrict__ rowptr, int n, int nb) {
    int tid = threadIdx.x;
    int i = blockIdx.x * 512 + tid;
    if (i < n && blockIdx.x > 0) rowptr[i] += g_part[blockIdx.x - 1];
    if (i == 0) rowptr[n] = g_part[nb - 1];
}

__global__ void fill_kernel(const int* __restrict__ es, const int* __restrict__ ep) {
    int i = blockIdx.x * blockDim.x + threadIdx.x;
    if (i < NE) {
        int s = es[i], p = ep[i];
        int posP = atomicAdd(&g_curP[p], 1);
        g_csrP[g_rpP[p] + posP] = s;
        int posS = atomicAdd(&g_curS[s], 1);
        g_csrS[g_rpS[s] + posS] = p;
    }
}

// x_play = playlist_embed[playlist_node_id]
__global__ void gather_xplay_kernel(const float* __restrict__ pemb, const int* __restrict__ pid) {
    int i = blockIdx.x * blockDim.x + threadIdx.x;   // NP * 32 threads, float4 each
    if (i < NP * 32) {
        int row = i >> 5;
        int q = i & 31;
        int src = pid[row];
        float4 v = *(const float4*)(pemb + (size_t)src * FH + q * 4);
        *(float4*)(g_xplay + (size_t)row * FH + q * 4) = v;
    }
}

// ---------------- mean aggregation (warp per destination row) ----------------
__global__ void agg_mean_kernel(const float* __restrict__ src,
                                const int* __restrict__ rowptr,
                                const int* __restrict__ cols,
                                float* __restrict__ out, int nrows) {
    int warp = (blockIdx.x * blockDim.x + threadIdx.x) >> 5;
    int lane = threadIdx.x & 31;
    if (warp >= nrows) return;
    int beg = rowptr[warp], end = rowptr[warp + 1];
    float4 acc = make_float4(0.f, 0.f, 0.f, 0.f);
    int e = beg;
    for (; e + 3 < end; e += 4) {
        int c0 = cols[e], c1 = cols[e + 1], c2 = cols[e + 2], c3 = cols[e + 3];
        float4 v0 = *(const float4*)(src + (size_t)c0 * FH + lane * 4);
        float4 v1 = *(const float4*)(src + (size_t)c1 * FH + lane * 4);
        float4 v2 = *(const float4*)(src + (size_t)c2 * FH + lane * 4);
        float4 v3 = *(const float4*)(src + (size_t)c3 * FH + lane * 4);
        acc.x += (v0.x + v1.x) + (v2.x + v3.x);
        acc.y += (v0.y + v1.y) + (v2.y + v3.y);
        acc.z += (v0.z + v1.z) + (v2.z + v3.z);
        acc.w += (v0.w + v1.w) + (v2.w + v3.w);
    }
    for (; e < end; ++e) {
        int c0 = cols[e];
        float4 v0 = *(const float4*)(src + (size_t)c0 * FH + lane * 4);
        acc.x += v0.x; acc.y += v0.y; acc.z += v0.z; acc.w += v0.w;
    }
    int d = end - beg;
    float inv = 1.f / (float)(d > 0 ? d : 1);
    acc.x *= inv; acc.y *= inv; acc.z *= inv; acc.w *= inv;
    *(float4*)(out + (size_t)warp * FH + lane * 4) = acc;
}

// ---------------- 3xTF32 GEMM: out[M,128] = A0@W0 + A1@W1 + b (opt relu) ----------------
__device__ __forceinline__ void split_tf32(float f, unsigned& hi, unsigned& lo) {
    unsigned h;
    asm("cvt.rna.tf32.f32 %0, %1;" : "=r"(h) : "f"(f));
    float l = f - __uint_as_float(h);
    unsigned lw;
    asm("cvt.rna.tf32.f32 %0, %1;" : "=r"(lw) : "f"(l));
    hi = h; lo = lw;
}

#define MMA_TF32(acc, a, b0, b1)                                                   \
    asm volatile("mma.sync.aligned.m16n8k8.row.col.f32.tf32.tf32.f32 "             \
                 "{%0,%1,%2,%3},{%4,%5,%6,%7},{%8,%9},{%0,%1,%2,%3};"              \
                 : "+f"(acc[0]), "+f"(acc[1]), "+f"(acc[2]), "+f"(acc[3])          \
                 : "r"(a[0]), "r"(a[1]), "r"(a[2]), "r"(a[3]), "r"(b0), "r"(b1))

#define AS_LD 44   // padded stride for A smem (conflict-free fragment loads)
#define BS_LD 136  // padded stride for B smem

__global__ __launch_bounds__(256)
void gemm_dual_kernel(const float* __restrict__ A0, const float* __restrict__ A1,
                      const float* __restrict__ W0, const float* __restrict__ W1,
                      const float* __restrict__ bias,
                      float* __restrict__ out, int M, int do_relu) {
    __shared__ float As[128 * AS_LD];
    __shared__ float Bs[32 * BS_LD];
    __shared__ float bias_s[128];

    int tid = threadIdx.x;
    int lane = tid & 31;
    int wid = tid >> 5;
    int warp_m = wid & 3;    // 4 warps along M (32 rows each)
    int warp_n = wid >> 2;   // 2 warps along N (64 cols each)
    int g = lane >> 2;       // groupID
    int r = lane & 3;        // thread in group
    int blockRow = blockIdx.x * 128;

    if (tid < 128) bias_s[tid] = bias[tid];

    float acc[2][8][4];
#pragma unroll
    for (int mt = 0; mt < 2; ++mt)
#pragma unroll
        for (int nt = 0; nt < 8; ++nt)
#pragma unroll
            for (int j = 0; j < 4; ++j) acc[mt][nt][j] = 0.f;

#pragma unroll
    for (int seg = 0; seg < 2; ++seg) {
        const float* Aseg = seg ? A1 : A0;
        const float* Wseg = seg ? W1 : W0;
#pragma unroll
        for (int kc = 0; kc < 4; ++kc) {
            __syncthreads();
            // load A tile [128 rows x 32 k] (fp32)
#pragma unroll
            for (int rr = 0; rr < 4; ++rr) {
                int idx = rr * 256 + tid;      // 0..1023 float4 slots
                int m = idx >> 3;
                int kq = idx & 7;
                int grow = blockRow + m;
                float4 v = make_float4(0.f, 0.f, 0.f, 0.f);
                if (grow < M)
                    v = *(const float4*)(Aseg + (size_t)grow * 128 + kc * 32 + kq * 4);
                *(float4*)(&As[m * AS_LD + kq * 4]) = v;
            }
            // load W tile [32 k x 128 n]
#pragma unroll
            for (int rr = 0; rr < 4; ++rr) {
                int idx = rr * 256 + tid;
                int kr = idx >> 5;
                int nq = idx & 31;
                float4 v = *(const float4*)(Wseg + (size_t)(kc * 32 + kr) * 128 + nq * 4);
                *(float4*)(&Bs[kr * BS_LD + nq * 4]) = v;
            }
            __syncthreads();

#pragma unroll
            for (int k8 = 0; k8 < 4; ++k8) {
                int k0 = k8 * 8;
                unsigned ahi[2][4], alo[2][4];
#pragma unroll
                for (int mt = 0; mt < 2; ++mt) {
                    int mb = warp_m * 32 + mt * 16;
                    float f0 = As[(mb + g) * AS_LD + k0 + r];
                    float f1 = As[(mb + g + 8) * AS_LD + k0 + r];
                    float f2 = As[(mb + g) * AS_LD + k0 + r + 4];
                    float f3 = As[(mb + g + 8) * AS_LD + k0 + r + 4];
                    split_tf32(f0, ahi[mt][0], alo[mt][0]);
                    split_tf32(f1, ahi[mt][1], alo[mt][1]);
                    split_tf32(f2, ahi[mt][2], alo[mt][2]);
                    split_tf32(f3, ahi[mt][3], alo[mt][3]);
                }
#pragma unroll
                for (int nt = 0; nt < 8; ++nt) {
                    int nb = warp_n * 64 + nt * 8;
                    float fb0 = Bs[(k0 + r) * BS_LD + nb + g];
                    float fb1 = Bs[(k0 + r + 4) * BS_LD + nb + g];
                    unsigned bh0, bl0, bh1, bl1;
                    split_tf32(fb0, bh0, bl0);
                    split_tf32(fb1, bh1, bl1);
#pragma unroll
                    for (int mt = 0; mt < 2; ++mt) {
                        MMA_TF32(acc[mt][nt], ahi[mt], bh0, bh1);   // hi*hi
                        MMA_TF32(acc[mt][nt], ahi[mt], bl0, bl1);   // hi*lo
                        MMA_TF32(acc[mt][nt], alo[mt], bh0, bh1);   // lo*hi
                    }
                }
            }
        }
    }

    // epilogue
#pragma unroll
    for (int mt = 0; mt < 2; ++mt) {
#pragma unroll
        for (int nt = 0; nt < 8; ++nt) {
            int col = warp_n * 64 + nt * 8 + r * 2;
            float bv0 = bias_s[col], bv1 = bias_s[col + 1];
            int row0 = blockRow + warp_m * 32 + mt * 16 + g;
            int row1 = row0 + 8;
            float v0 = acc[mt][nt][0] + bv0;
            float v1 = acc[mt][nt][1] + bv1;
            float v2 = acc[mt][nt][2] + bv0;
            float v3 = acc[mt][nt][3] + bv1;
            if (do_relu) {
                v0 = fmaxf(v0, 0.f); v1 = fmaxf(v1, 0.f);
                v2 = fmaxf(v2, 0.f); v3 = fmaxf(v3, 0.f);
            }
            if (row0 < M) *(float2*)(out + (size_t)row0 * 128 + col) = make_float2(v0, v1);
            if (row1 < M) *(float2*)(out + (size_t)row1 * 128 + col) = make_float2(v2, v3);
        }
    }
}

// ---------------- host launcher ----------------
static float* sym_f(const void* s) { void* p = nullptr; cudaGetSymbolAddress(&p, s); return (float*)p; }
static int*   sym_i(const void* s) { void* p = nullptr; cudaGetSymbolAddress(&p, s); return (int*)p; }

extern "C" void kernel_launch(void* const* d_in, const int* in_sizes, int n_in,
                              void* d_out, int out_size) {
    const float* song_x  = (const float*)d_in[0];
    const int*   pid     = (const int*)d_in[1];
    const int*   e_song  = (const int*)d_in[2];
    const int*   e_play  = (const int*)d_in[3];
    const float* pemb    = (const float*)d_in[4];
    const float* Wl1_sp  = (const float*)d_in[5];
    const float* Wr1_sp  = (const float*)d_in[6];
    const float* b1_sp   = (const float*)d_in[7];
    const float* Wl1_ps  = (const float*)d_in[8];
    const float* Wr1_ps  = (const float*)d_in[9];
    const float* b1_ps   = (const float*)d_in[10];
    const float* Wl2_sp  = (const float*)d_in[11];
    const float* Wr2_sp  = (const float*)d_in[12];
    const float* b2_sp   = (const float*)d_in[13];
    const float* Wl2_ps  = (const float*)d_in[14];
    const float* Wr2_ps  = (const float*)d_in[15];
    const float* b2_ps   = (const float*)d_in[16];

    float* out = (float*)d_out;
    float* out_s2 = out;                      // [NS,128] first
    float* out_p2 = out + (size_t)NS * FH;    // [NP,128] second

    float* xplay = sym_f(g_xplay);
    float* aggP  = sym_f(g_aggP);
    float* aggS  = sym_f(g_aggS);
    float* p1    = sym_f(g_p1);
    float* s1    = sym_f(g_s1);
    int*   cntP  = sym_i(g_cntP);
    int*   cntS  = sym_i(g_cntS);
    int*   rpP   = sym_i(g_rpP);
    int*   rpS   = sym_i(g_rpS);
    int*   csrP  = sym_i(g_csrP);
    int*   csrS  = sym_i(g_csrS);

    // ---- CSR build (shared by both layers) ----
    zero_misc_kernel<<<(NS + 255) / 256, 256>>>();
    hist_kernel<<<(NE + 255) / 256, 256>>>(e_song, e_play);

    int nbP = (NP + 511) / 512;   // 40
    scan1_kernel<<<nbP, 512>>>(cntP, rpP, NP);
    scan2_kernel<<<1, 256>>>(nbP);
    scan3_kernel<<<nbP, 512>>>(rpP, NP, nbP);

    int nbS = (NS + 511) / 512;   // 196
    scan1_kernel<<<nbS, 512>>>(cntS, rpS, NS);
    scan2_kernel<<<1, 256>>>(nbS);
    scan3_kernel<<<nbS, 512>>>(rpS, NS, nbS);

    fill_kernel<<<(NE + 255) / 256, 256>>>(e_song, e_play);
    gather_xplay_kernel<<<(NP * 32 + 255) / 256, 256>>>(pemb, pid);

    const int AGG_WPB = 8;  // warps per block
    // ---- conv1 ----
    agg_mean_kernel<<<(NP + AGG_WPB - 1) / AGG_WPB, AGG_WPB * 32>>>(song_x, rpP, csrP, aggP, NP);
    gemm_dual_kernel<<<(NP + 127) / 128, 256>>>(aggP, xplay, Wl1_sp, Wr1_sp, b1_sp, p1, NP, 1);
    agg_mean_kernel<<<(NS + AGG_WPB - 1) / AGG_WPB, AGG_WPB * 32>>>(xplay, rpS, csrS, aggS, NS);
    gemm_dual_kernel<<<(NS + 127) / 128, 256>>>(aggS, song_x, Wl1_ps, Wr1_ps, b1_ps, s1, NS, 1);

    // ---- conv2 ----
    agg_mean_kernel<<<(NP + AGG_WPB - 1) / AGG_WPB, AGG_WPB * 32>>>(s1, rpP, csrP, aggP, NP);
    gemm_dual_kernel<<<(NP + 127) / 128, 256>>>(aggP, p1, Wl2_sp, Wr2_sp, b2_sp, out_p2, NP, 0);
    agg_mean_kernel<<<(NS + AGG_WPB - 1) / AGG_WPB, AGG_WPB * 32>>>(p1, rpS, csrS, aggS, NS);
    gemm_dual_kernel<<<(NS + 127) / 128, 256>>>(aggS, s1, Wl2_ps, Wr2_ps, b2_ps, out_s2, NS, 0);

    (void)in_sizes; (void)n_in; (void)out_size;
}